// round 15
// baseline (speedup 1.0000x reference)
#include <cuda_runtime.h>
#include <cuda_bf16.h>
#include <math.h>
#include <stdint.h>

#define BB 1024
#define SS 200
#define II 4
#define HH 128
#define SH (SS*HH)          // 25600
#define WS (II*HH*HH)       // 65536
#define NITEM (BB*II)
#define ITEM_N (BB*SS*HH)   // 26,214,400
#define W_N    (SS*II*HH*HH) // 13,107,200

__device__ float g_hat[(size_t)BB * II * SS * HH];   // [b][i][s][h], 419 MB
__device__ __nv_bfloat16 g_item_hi[ITEM_N];
__device__ __nv_bfloat16 g_item_lo[ITEM_N];
__device__ __nv_bfloat16 g_w_hi[W_N];
__device__ __nv_bfloat16 g_w_lo[W_N];

// ---------------------------------------------------------------------------
// helpers (plain sm_103-legal PTX only)
// ---------------------------------------------------------------------------
__device__ __forceinline__ uint32_t smem_u32(const void* p) {
    uint32_t a;
    asm("{ .reg .u64 t; cvta.to.shared.u64 t, %1; cvt.u32.u64 %0, t; }"
        : "=r"(a) : "l"(p));
    return a;
}
__device__ __forceinline__ void ldm4(uint32_t* r, uint32_t addr) {
    asm volatile("ldmatrix.sync.aligned.m8n8.x4.shared.b16 {%0,%1,%2,%3}, [%4];"
        : "=r"(r[0]), "=r"(r[1]), "=r"(r[2]), "=r"(r[3]) : "r"(addr));
}
__device__ __forceinline__ void mma16816(float* c, const uint32_t* a, const uint32_t* b) {
    asm volatile(
        "mma.sync.aligned.m16n8k16.row.col.f32.bf16.bf16.f32 "
        "{%0,%1,%2,%3}, {%4,%5,%6,%7}, {%8,%9}, {%0,%1,%2,%3};"
        : "+f"(c[0]), "+f"(c[1]), "+f"(c[2]), "+f"(c[3])
        : "r"(a[0]), "r"(a[1]), "r"(a[2]), "r"(a[3]), "r"(b[0]), "r"(b[1]));
}
__device__ __forceinline__ void mbar_init(uint32_t mbar, uint32_t cnt) {
    asm volatile("mbarrier.init.shared.b64 [%0], %1;" :: "r"(mbar), "r"(cnt) : "memory");
}
__device__ __forceinline__ void mbar_expect_tx(uint32_t mbar, uint32_t bytes) {
    asm volatile("mbarrier.arrive.expect_tx.shared.b64 _, [%0], %1;"
                 :: "r"(mbar), "r"(bytes) : "memory");
}
__device__ __forceinline__ void mbar_wait(uint32_t mbar, uint32_t parity) {
    asm volatile("{\n\t.reg .pred P;\n\t"
        "W_%=:\n\t"
        "mbarrier.try_wait.parity.acquire.cta.shared::cta.b64 P, [%0], %1, 0x989680;\n\t"
        "@P bra.uni D_%=;\n\t"
        "bra.uni W_%=;\n\t"
        "D_%=:\n\t}" :: "r"(mbar), "r"(parity) : "memory");
}
__device__ __forceinline__ void bulk_g2s(uint32_t dst, const void* src,
                                         uint32_t bytes, uint32_t mbar) {
    asm volatile(
        "cp.async.bulk.shared::cta.global.mbarrier::complete_tx::bytes [%0], [%1], %2, [%3];"
        :: "r"(dst), "l"(src), "r"(bytes), "r"(mbar) : "memory");
}
__device__ __forceinline__ float warp_sum(float v) {
    #pragma unroll
    for (int o = 16; o > 0; o >>= 1) v += __shfl_xor_sync(0xffffffffu, v, o);
    return v;
}
__device__ __forceinline__ float warp_max(float v) {
    #pragma unroll
    for (int o = 16; o > 0; o >>= 1) v = fmaxf(v, __shfl_xor_sync(0xffffffffu, v, o));
    return v;
}
__device__ __forceinline__ uint32_t pack2(__nv_bfloat16 a, __nv_bfloat16 b) {
    __nv_bfloat162 t; t.x = a; t.y = b;
    return *(uint32_t*)&t;
}

// ---------------------------------------------------------------------------
// Phase 0: one-shot f32 -> bf16 hi/lo conversion (each element ONCE).
// ---------------------------------------------------------------------------
#define CVT_BLOCKS ((ITEM_N/4 + W_N/4) / 256)   // 38400 exactly

__global__ __launch_bounds__(256)
void convert_kernel(const float* __restrict__ item, const float* __restrict__ w)
{
    const int64_t n_item4 = ITEM_N / 4;
    int64_t idx = (int64_t)blockIdx.x * 256 + threadIdx.x;

    float4 v;
    __nv_bfloat16 *hi, *lo;
    int64_t e;
    if (idx < n_item4) {
        v = ((const float4*)item)[idx];
        e = idx * 4; hi = g_item_hi; lo = g_item_lo;
    } else {
        int64_t j = idx - n_item4;
        v = ((const float4*)w)[j];
        e = j * 4; hi = g_w_hi; lo = g_w_lo;
    }
    __nv_bfloat16 h0 = __float2bfloat16(v.x), h1 = __float2bfloat16(v.y);
    __nv_bfloat16 h2 = __float2bfloat16(v.z), h3 = __float2bfloat16(v.w);
    __nv_bfloat16 l0 = __float2bfloat16(v.x - __bfloat162float(h0));
    __nv_bfloat16 l1 = __float2bfloat16(v.y - __bfloat162float(h1));
    __nv_bfloat16 l2 = __float2bfloat16(v.z - __bfloat162float(h2));
    __nv_bfloat16 l3 = __float2bfloat16(v.w - __bfloat162float(h3));
    *(uint2*)(hi + e) = make_uint2(pack2(h0, h1), pack2(h2, h3));
    *(uint2*)(lo + e) = make_uint2(pack2(l0, l1), pack2(l2, l3));
}

// ---------------------------------------------------------------------------
// Phase 1: bf16-split HMMA GEMM — loads pre-converted bf16 (no in-kernel cvt).
// Block = (btile, jt): M=128, N=64, K=128. MMA/epilogue identical to R11.
// ---------------------------------------------------------------------------
#define PITCH 136
#define AT_B (128 * PITCH * 2)
#define BT_B (64  * PITCH * 2)
#define A_HI 0
#define A_LO (AT_B)
#define B_HI (2*AT_B)
#define B_LO (2*AT_B + BT_B)
#define SMEM_GEMM (2*AT_B + 2*BT_B)   // 104448

__global__ __launch_bounds__(256, 2)
void gemm_hat_mma()
{
    extern __shared__ __align__(16) char smp[];
    const uint32_t sbase = smem_u32(smp);

    const int tid   = threadIdx.x;
    const int wid   = tid >> 5;
    const int lane  = tid & 31;
    const int btile = blockIdx.x >> 3;
    const int jt    = blockIdx.x & 7;
    const int s     = blockIdx.y;
    const int b0    = btile << 7;
    const int cap_i = jt >> 1;

    // ---- plain copies: global bf16 hi/lo -> pitched smem (uint4 = 8 bf16) ----
    const __nv_bfloat16* gah = g_item_hi + (size_t)b0 * SH + (size_t)s * HH;
    const __nv_bfloat16* gal = g_item_lo + (size_t)b0 * SH + (size_t)s * HH;
    const __nv_bfloat16* gwh = g_w_hi + (size_t)s * WS + (size_t)jt * (64 * HH);
    const __nv_bfloat16* gwl = g_w_lo + (size_t)s * WS + (size_t)jt * (64 * HH);

    #pragma unroll
    for (int q = 0; q < 8; q++) {               // A: 128 rows x 16 chunks
        int idx = q * 256 + tid;
        int row = idx >> 4;
        int k8  = (idx & 15) << 3;
        uint32_t soff = (uint32_t)row * (PITCH*2) + (uint32_t)k8 * 2;
        *(uint4*)(smp + A_HI + soff) = *(const uint4*)(gah + (size_t)row * SH + k8);
        *(uint4*)(smp + A_LO + soff) = *(const uint4*)(gal + (size_t)row * SH + k8);
    }
    #pragma unroll
    for (int q = 0; q < 4; q++) {               // B: 64 rows x 16 chunks
        int idx = q * 256 + tid;
        int row = idx >> 4;
        int k8  = (idx & 15) << 3;
        uint32_t soff = (uint32_t)row * (PITCH*2) + (uint32_t)k8 * 2;
        *(uint4*)(smp + B_HI + soff) = *(const uint4*)(gwh + row * HH + k8);
        *(uint4*)(smp + B_LO + soff) = *(const uint4*)(gwl + row * HH + k8);
    }
    __syncthreads();

    const int mw = (wid & 3) * 32;
    const int nw = (wid >> 2) * 32;

    float acc[2][4][4];
    #pragma unroll
    for (int mt = 0; mt < 2; mt++)
        #pragma unroll
        for (int nt = 0; nt < 4; nt++)
            #pragma unroll
            for (int c = 0; c < 4; c++) acc[mt][nt][c] = 0.f;

    #pragma unroll
    for (int ks = 0; ks < 8; ks++) {
        const int k0 = ks * 16;
        uint32_t ah[2][4], al[2][4];
        {
            uint32_t aoff = (uint32_t)(mw + (lane & 15)) * (PITCH*2)
                          + (uint32_t)(k0 + ((lane >> 4) << 3)) * 2;
            ldm4(ah[0], sbase + A_HI + aoff);
            ldm4(ah[1], sbase + A_HI + aoff + 16 * (PITCH*2));
            ldm4(al[0], sbase + A_LO + aoff);
            ldm4(al[1], sbase + A_LO + aoff + 16 * (PITCH*2));
        }
        uint32_t bh[2][4], bl[2][4];
        {
            uint32_t boff = (uint32_t)(nw + ((lane >> 4) << 3) + (lane & 7)) * (PITCH*2)
                          + (uint32_t)(k0 + (((lane >> 3) & 1) << 3)) * 2;
            #pragma unroll
            for (int p = 0; p < 2; p++) {
                ldm4(bh[p], sbase + B_HI + boff + (uint32_t)p * 16 * (PITCH*2));
                ldm4(bl[p], sbase + B_LO + boff + (uint32_t)p * 16 * (PITCH*2));
            }
        }
        #pragma unroll
        for (int mt = 0; mt < 2; mt++)
            #pragma unroll
            for (int nt = 0; nt < 4; nt++) {
                const uint32_t* bhp = &bh[nt >> 1][(nt & 1) * 2];
                const uint32_t* blp = &bl[nt >> 1][(nt & 1) * 2];
                mma16816(acc[mt][nt], ah[mt], bhp);
                mma16816(acc[mt][nt], ah[mt], blp);
                mma16816(acc[mt][nt], al[mt], bhp);
            }
    }

    const int g = lane >> 2, t = lane & 3;
    const int hbase = (jt & 1) * 64 + nw;
    #pragma unroll
    for (int mt = 0; mt < 2; mt++) {
        int rowm = mw + mt * 16 + g;
        size_t p0 = ((size_t)(b0 + rowm) * II + cap_i) * SH + (size_t)s * HH + hbase;
        size_t p1 = p0 + (size_t)8 * II * SH;
        #pragma unroll
        for (int nt = 0; nt < 4; nt++) {
            *(float2*)(g_hat + p0 + nt * 8 + 2 * t) =
                make_float2(acc[mt][nt][0], acc[mt][nt][1]);
            *(float2*)(g_hat + p1 + nt * 8 + 2 * t) =
                make_float2(acc[mt][nt][2], acc[mt][nt][3]);
        }
    }
}

// ---------------------------------------------------------------------------
// Phase 2: routing — R11 verbatim (best measured: 146.2 us).
// ---------------------------------------------------------------------------
#define NBLK 148
#define HATB (SS*HH*4)
#define G_HAT  0
#define G_CAPP (SS*HH)                 // [16][128]
#define G_CW   (G_CAPP + 2048)
#define G_SWT  (G_CW + SS)
#define G_MSK  (G_SWT + SS)
#define G_CAP  (G_MSK + SS)            // float idx 28248 -> byte 112992, 16B-aligned
#define GSZ    (G_CAP + 128)           // 28376 floats = 113504 B
#define R_MB   (2 * GSZ * 4)
#define SMEM_ROUTE (R_MB + 32)

__global__ __launch_bounds__(1024, 1)
void routing_kernel(const int* __restrict__ mask, float* __restrict__ out)
{
    extern __shared__ __align__(16) float sm[];
    const uint32_t sb = smem_u32(sm);

    const int tid  = threadIdx.x;
    const int gid  = tid >> 9;
    const int t    = tid & 511;
    const int lane = t & 31;

    float*  gbase = sm + gid * GSZ;
    float4* hs4   = (float4*)(gbase + G_HAT);
    float4* capp4 = (float4*)(gbase + G_CAPP);
    float*  cw    = gbase + G_CW;
    float*  swt   = gbase + G_SWT;
    float*  mskf  = gbase + G_MSK;
    float4* cap4  = (float4*)(gbase + G_CAP);
    float*  capf  = gbase + G_CAP;
    const uint32_t mbar = sb + R_MB + gid * 8;
    const uint32_t hsb  = sb + (uint32_t)(gid * GSZ) * 4;

    if (tid == 0) {
        mbar_init(sb + R_MB, 1);
        mbar_init(sb + R_MB + 8, 1);
        asm volatile("fence.proxy.async.shared::cta;" ::: "memory");
    }
    __syncthreads();

    #define BARG() asm volatile("bar.sync %0, 512;" :: "r"(gid + 1) : "memory")

    const float NEG_INF = __int_as_float(0xff800000);
    uint32_t phase = 0;
    const int worker = blockIdx.x * 2 + gid;
    const int step   = NBLK * 2;

    if (worker < NITEM && t == 0) {
        mbar_expect_tx(mbar, HATB);
        bulk_g2s(hsb, g_hat + (size_t)worker * SH, HATB, mbar);
    }

    for (int w = worker; w < NITEM; w += step) {
        const int my_mask = (t < SS) ? mask[(w >> 2) * SS + t] : 0;
        if (t < SS) mskf[t] = my_mask ? 1.f : 0.f;   // ordered by it0's BARG
        const int wn = w + step;

        mbar_wait(mbar, phase);
        phase ^= 1;

        for (int it = 0; it < 3; it++) {
            if (it == 0) {
                // cw == 0 -> uniform softmax, then masked
                if (t < SS) swt[t] = my_mask ? (1.f / SS) : 0.f;
                BARG();
            } else {
                // single-warp softmax: warp 0 holds all 200 cw in registers
                if (t < 32) {
                    float v[7];
                    float mx = NEG_INF;
                    #pragma unroll
                    for (int j = 0; j < 7; j++) {
                        int idx = j * 32 + lane;
                        v[j] = (idx < SS) ? cw[idx] : NEG_INF;
                        mx = fmaxf(mx, v[j]);
                    }
                    mx = warp_max(mx);
                    float sum = 0.f;
                    #pragma unroll
                    for (int j = 0; j < 7; j++) {
                        v[j] = (j * 32 + lane < SS) ? __expf(v[j] - mx) : 0.f;
                        sum += v[j];
                    }
                    sum = warp_sum(sum);
                    float inv = 1.f / sum;
                    #pragma unroll
                    for (int j = 0; j < 7; j++) {
                        int idx = j * 32 + lane;
                        if (idx < SS) swt[idx] = v[j] * inv * mskf[idx];
                    }
                }
                BARG();
            }

            // cap partials: 32 col-groups x 16 s-slices
            {
                int g = t & 31, sl = t >> 5;
                float4 acc = make_float4(0.f, 0.f, 0.f, 0.f);
                for (int s2 = sl; s2 < SS; s2 += 16) {
                    float sv = swt[s2];
                    float4 hv = hs4[s2 * 32 + g];
                    acc.x = fmaf(sv, hv.x, acc.x);
                    acc.y = fmaf(sv, hv.y, acc.y);
                    acc.z = fmaf(sv, hv.z, acc.z);
                    acc.w = fmaf(sv, hv.w, acc.w);
                }
                capp4[sl * 32 + g] = acc;
            }
            BARG();

            // last hat read for it2 done -> prefetch next item
            if (it == 2 && wn < NITEM && t == 0) {
                mbar_expect_tx(mbar, HATB);
                bulk_g2s(hsb, g_hat + (size_t)wn * SH, HATB, mbar);
            }

            // reduce + squash (warp 0 of group)
            if (t < 32) {
                float4 r = make_float4(0.f, 0.f, 0.f, 0.f);
                #pragma unroll
                for (int sl = 0; sl < 16; sl++) {
                    float4 tv = capp4[sl * 32 + t];
                    r.x += tv.x; r.y += tv.y; r.z += tv.z; r.w += tv.w;
                }
                float np = r.x * r.x + r.y * r.y + r.z * r.z + r.w * r.w;
                float nn = warp_sum(np);
                float f = nn / (1.f + nn) * rsqrtf(nn + 1e-9f);
                cap4[t] = make_float4(r.x * f, r.y * f, r.z * f, r.w * f);
            }
            BARG();

            // delta: per-thread dot, t-swizzled j (conflict-free)
            if (it < 2) {
                if (t < SS) {
                    const float4* hrow = hs4 + t * 32;
                    float a0 = 0.f, a1 = 0.f, a2 = 0.f, a3 = 0.f;
                    #pragma unroll 8
                    for (int j0 = 0; j0 < 32; j0++) {
                        int j = (j0 + t) & 31;
                        float4 hv = hrow[j];
                        float4 cv = cap4[j];
                        a0 = fmaf(hv.x, cv.x, a0);
                        a1 = fmaf(hv.y, cv.y, a1);
                        a2 = fmaf(hv.z, cv.z, a2);
                        a3 = fmaf(hv.w, cv.w, a3);
                    }
                    float d = (a0 + a1) + (a2 + a3);
                    cw[t] = (it == 0) ? d : cw[t] + d;
                }
                BARG();
            }
        }

        if (t < 128)
            out[(size_t)w * HH + t] = capf[t];
        BARG();
    }
    #undef BARG
}

// ---------------------------------------------------------------------------
extern "C" void kernel_launch(void* const* d_in, const int* in_sizes, int n_in,
                              void* d_out, int out_size)
{
    const float* item = (const float*)d_in[0];
    const int*   mask = (const int*)d_in[1];
    const float* w    = (const float*)d_in[2];
    float*       out  = (float*)d_out;

    cudaFuncSetAttribute(gemm_hat_mma,
                         cudaFuncAttributeMaxDynamicSharedMemorySize, SMEM_GEMM);
    cudaFuncSetAttribute(routing_kernel,
                         cudaFuncAttributeMaxDynamicSharedMemorySize, SMEM_ROUTE);

    convert_kernel<<<CVT_BLOCKS, 256>>>(item, w);

    dim3 ggrid(64, SS);
    gemm_hat_mma<<<ggrid, 256, SMEM_GEMM>>>();

    routing_kernel<<<NBLK, 1024, SMEM_ROUTE>>>(mask, out);
}

// round 16
// speedup vs baseline: 1.0821x; 1.0821x over previous
#include <cuda_runtime.h>
#include <cuda_bf16.h>
#include <math.h>
#include <stdint.h>

#define BB 1024
#define SS 200
#define II 4
#define HH 128
#define SH (SS*HH)          // 25600
#define WS (II*HH*HH)       // 65536
#define NITEM (BB*II)

__device__ float g_hat[(size_t)BB * II * SS * HH];   // [b][i][s][h], 419 MB

// ---------------------------------------------------------------------------
// helpers (plain sm_103-legal PTX only)
// ---------------------------------------------------------------------------
__device__ __forceinline__ uint32_t smem_u32(const void* p) {
    uint32_t a;
    asm("{ .reg .u64 t; cvta.to.shared.u64 t, %1; cvt.u32.u64 %0, t; }"
        : "=r"(a) : "l"(p));
    return a;
}
__device__ __forceinline__ void ldm4(uint32_t* r, uint32_t addr) {
    asm volatile("ldmatrix.sync.aligned.m8n8.x4.shared.b16 {%0,%1,%2,%3}, [%4];"
        : "=r"(r[0]), "=r"(r[1]), "=r"(r[2]), "=r"(r[3]) : "r"(addr));
}
__device__ __forceinline__ void mma16816(float* c, const uint32_t* a, const uint32_t* b) {
    asm volatile(
        "mma.sync.aligned.m16n8k16.row.col.f32.bf16.bf16.f32 "
        "{%0,%1,%2,%3}, {%4,%5,%6,%7}, {%8,%9}, {%0,%1,%2,%3};"
        : "+f"(c[0]), "+f"(c[1]), "+f"(c[2]), "+f"(c[3])
        : "r"(a[0]), "r"(a[1]), "r"(a[2]), "r"(a[3]), "r"(b[0]), "r"(b[1]));
}
__device__ __forceinline__ void mbar_init(uint32_t mbar, uint32_t cnt) {
    asm volatile("mbarrier.init.shared.b64 [%0], %1;" :: "r"(mbar), "r"(cnt) : "memory");
}
__device__ __forceinline__ void mbar_expect_tx(uint32_t mbar, uint32_t bytes) {
    asm volatile("mbarrier.arrive.expect_tx.shared.b64 _, [%0], %1;"
                 :: "r"(mbar), "r"(bytes) : "memory");
}
__device__ __forceinline__ void mbar_wait(uint32_t mbar, uint32_t parity) {
    asm volatile("{\n\t.reg .pred P;\n\t"
        "W_%=:\n\t"
        "mbarrier.try_wait.parity.acquire.cta.shared::cta.b64 P, [%0], %1, 0x989680;\n\t"
        "@P bra.uni D_%=;\n\t"
        "bra.uni W_%=;\n\t"
        "D_%=:\n\t}" :: "r"(mbar), "r"(parity) : "memory");
}
__device__ __forceinline__ void bulk_g2s(uint32_t dst, const void* src,
                                         uint32_t bytes, uint32_t mbar) {
    asm volatile(
        "cp.async.bulk.shared::cta.global.mbarrier::complete_tx::bytes [%0], [%1], %2, [%3];"
        :: "r"(dst), "l"(src), "r"(bytes), "r"(mbar) : "memory");
}
__device__ __forceinline__ float warp_sum(float v) {
    #pragma unroll
    for (int o = 16; o > 0; o >>= 1) v += __shfl_xor_sync(0xffffffffu, v, o);
    return v;
}
__device__ __forceinline__ float warp_max(float v) {
    #pragma unroll
    for (int o = 16; o > 0; o >>= 1) v = fmaxf(v, __shfl_xor_sync(0xffffffffu, v, o));
    return v;
}

// ---------------------------------------------------------------------------
// Phase 1: bf16-split HMMA GEMM (R11 structure; inner mma loop reordered:
// product-major so consecutive mmas hit 8 distinct accumulators).
// ---------------------------------------------------------------------------
#define PITCH 136
#define AT_B (128 * PITCH * 2)
#define BT_B (64  * PITCH * 2)
#define A_HI 0
#define A_LO (AT_B)
#define B_HI (2*AT_B)
#define B_LO (2*AT_B + BT_B)
#define SMEM_GEMM (2*AT_B + 2*BT_B)   // 104448

__device__ __forceinline__ uint32_t pack2(__nv_bfloat16 a, __nv_bfloat16 b) {
    __nv_bfloat162 t; t.x = a; t.y = b;
    return *(uint32_t*)&t;
}
__device__ __forceinline__ void split_store(char* hi, char* lo, int row, int k, float4 v) {
    __nv_bfloat16 h0 = __float2bfloat16(v.x), h1 = __float2bfloat16(v.y);
    __nv_bfloat16 h2 = __float2bfloat16(v.z), h3 = __float2bfloat16(v.w);
    __nv_bfloat16 l0 = __float2bfloat16(v.x - __bfloat162float(h0));
    __nv_bfloat16 l1 = __float2bfloat16(v.y - __bfloat162float(h1));
    __nv_bfloat16 l2 = __float2bfloat16(v.z - __bfloat162float(h2));
    __nv_bfloat16 l3 = __float2bfloat16(v.w - __bfloat162float(h3));
    uint32_t off = (uint32_t)row * (PITCH*2) + (uint32_t)k * 2;
    *(uint2*)(hi + off) = make_uint2(pack2(h0, h1), pack2(h2, h3));
    *(uint2*)(lo + off) = make_uint2(pack2(l0, l1), pack2(l2, l3));
}

__global__ __launch_bounds__(256, 2)
void gemm_hat_mma(const float* __restrict__ item, const float* __restrict__ w)
{
    extern __shared__ __align__(16) char smp[];
    const uint32_t sbase = smem_u32(smp);

    const int tid   = threadIdx.x;
    const int wid   = tid >> 5;
    const int lane  = tid & 31;
    const int btile = blockIdx.x >> 3;
    const int jt    = blockIdx.x & 7;
    const int s     = blockIdx.y;
    const int b0    = btile << 7;
    const int cap_i = jt >> 1;

    const float* ga = item + (size_t)b0 * SH + (size_t)s * HH;
    const float* gw = w + (size_t)s * WS + (size_t)jt * (64 * HH);
    #pragma unroll
    for (int q = 0; q < 8; q++) {
        int idx = q * 512 + tid;
        int row = idx >> 5;
        int k4  = (idx & 31) << 2;
        float4 av = *(const float4*)(ga + (size_t)row * SH + k4);
        split_store(smp + A_HI, smp + A_LO, row, k4, av);
        int idx2 = idx + 256;
        int row2 = idx2 >> 5;
        int k42  = (idx2 & 31) << 2;
        float4 av2 = *(const float4*)(ga + (size_t)row2 * SH + k42);
        split_store(smp + A_HI, smp + A_LO, row2, k42, av2);
    }
    #pragma unroll
    for (int q = 0; q < 8; q++) {
        int idx = q * 256 + tid;
        int row = idx >> 5;
        int k4  = (idx & 31) << 2;
        float4 wv = *(const float4*)(gw + row * HH + k4);
        split_store(smp + B_HI, smp + B_LO, row, k4, wv);
    }
    __syncthreads();

    const int mw = (wid & 3) * 32;
    const int nw = (wid >> 2) * 32;

    float acc[2][4][4];
    #pragma unroll
    for (int mt = 0; mt < 2; mt++)
        #pragma unroll
        for (int nt = 0; nt < 4; nt++)
            #pragma unroll
            for (int c = 0; c < 4; c++) acc[mt][nt][c] = 0.f;

    #pragma unroll
    for (int ks = 0; ks < 8; ks++) {
        const int k0 = ks * 16;
        uint32_t ah[2][4], al[2][4];
        {
            uint32_t aoff = (uint32_t)(mw + (lane & 15)) * (PITCH*2)
                          + (uint32_t)(k0 + ((lane >> 4) << 3)) * 2;
            ldm4(ah[0], sbase + A_HI + aoff);
            ldm4(ah[1], sbase + A_HI + aoff + 16 * (PITCH*2));
            ldm4(al[0], sbase + A_LO + aoff);
            ldm4(al[1], sbase + A_LO + aoff + 16 * (PITCH*2));
        }
        uint32_t bh[2][4], bl[2][4];
        {
            uint32_t boff = (uint32_t)(nw + ((lane >> 4) << 3) + (lane & 7)) * (PITCH*2)
                          + (uint32_t)(k0 + (((lane >> 3) & 1) << 3)) * 2;
            #pragma unroll
            for (int p = 0; p < 2; p++) {
                ldm4(bh[p], sbase + B_HI + boff + (uint32_t)p * 16 * (PITCH*2));
                ldm4(bl[p], sbase + B_LO + boff + (uint32_t)p * 16 * (PITCH*2));
            }
        }
        // product-major: consecutive mmas target 8 distinct accumulators;
        // per-accumulator order stays hh -> hl -> lh (bit-identical result)
        #pragma unroll
        for (int p = 0; p < 3; p++) {
            #pragma unroll
            for (int mt = 0; mt < 2; mt++)
                #pragma unroll
                for (int nt = 0; nt < 4; nt++) {
                    const uint32_t* ap = (p == 2) ? al[mt] : ah[mt];
                    const uint32_t* bp = (p == 1) ? &bl[nt >> 1][(nt & 1) * 2]
                                                  : &bh[nt >> 1][(nt & 1) * 2];
                    mma16816(acc[mt][nt], ap, bp);
                }
        }
    }

    const int g = lane >> 2, t = lane & 3;
    const int hbase = (jt & 1) * 64 + nw;
    #pragma unroll
    for (int mt = 0; mt < 2; mt++) {
        int rowm = mw + mt * 16 + g;
        size_t p0 = ((size_t)(b0 + rowm) * II + cap_i) * SH + (size_t)s * HH + hbase;
        size_t p1 = p0 + (size_t)8 * II * SH;
        #pragma unroll
        for (int nt = 0; nt < 4; nt++) {
            *(float2*)(g_hat + p0 + nt * 8 + 2 * t) =
                make_float2(acc[mt][nt][0], acc[mt][nt][1]);
            *(float2*)(g_hat + p1 + nt * 8 + 2 * t) =
                make_float2(acc[mt][nt][2], acc[mt][nt][3]);
        }
    }
}

// ---------------------------------------------------------------------------
// Phase 2: routing — R11 verbatim (best measured: 146.2 us).
// ---------------------------------------------------------------------------
#define NBLK 148
#define HATB (SS*HH*4)
#define G_HAT  0
#define G_CAPP (SS*HH)                 // [16][128]
#define G_CW   (G_CAPP + 2048)
#define G_SWT  (G_CW + SS)
#define G_MSK  (G_SWT + SS)
#define G_CAP  (G_MSK + SS)            // float idx 28248 -> byte 112992, 16B-aligned
#define GSZ    (G_CAP + 128)           // 28376 floats = 113504 B
#define R_MB   (2 * GSZ * 4)
#define SMEM_ROUTE (R_MB + 32)

__global__ __launch_bounds__(1024, 1)
void routing_kernel(const int* __restrict__ mask, float* __restrict__ out)
{
    extern __shared__ __align__(16) float sm[];
    const uint32_t sb = smem_u32(sm);

    const int tid  = threadIdx.x;
    const int gid  = tid >> 9;
    const int t    = tid & 511;
    const int lane = t & 31;

    float*  gbase = sm + gid * GSZ;
    float4* hs4   = (float4*)(gbase + G_HAT);
    float4* capp4 = (float4*)(gbase + G_CAPP);
    float*  cw    = gbase + G_CW;
    float*  swt   = gbase + G_SWT;
    float*  mskf  = gbase + G_MSK;
    float4* cap4  = (float4*)(gbase + G_CAP);
    float*  capf  = gbase + G_CAP;
    const uint32_t mbar = sb + R_MB + gid * 8;
    const uint32_t hsb  = sb + (uint32_t)(gid * GSZ) * 4;

    if (tid == 0) {
        mbar_init(sb + R_MB, 1);
        mbar_init(sb + R_MB + 8, 1);
        asm volatile("fence.proxy.async.shared::cta;" ::: "memory");
    }
    __syncthreads();

    #define BARG() asm volatile("bar.sync %0, 512;" :: "r"(gid + 1) : "memory")

    const float NEG_INF = __int_as_float(0xff800000);
    uint32_t phase = 0;
    const int worker = blockIdx.x * 2 + gid;
    const int step   = NBLK * 2;

    if (worker < NITEM && t == 0) {
        mbar_expect_tx(mbar, HATB);
        bulk_g2s(hsb, g_hat + (size_t)worker * SH, HATB, mbar);
    }

    for (int w = worker; w < NITEM; w += step) {
        const int my_mask = (t < SS) ? mask[(w >> 2) * SS + t] : 0;
        if (t < SS) mskf[t] = my_mask ? 1.f : 0.f;   // ordered by it0's BARG
        const int wn = w + step;

        mbar_wait(mbar, phase);
        phase ^= 1;

        for (int it = 0; it < 3; it++) {
            if (it == 0) {
                // cw == 0 -> uniform softmax, then masked
                if (t < SS) swt[t] = my_mask ? (1.f / SS) : 0.f;
                BARG();
            } else {
                // single-warp softmax: warp 0 holds all 200 cw in registers
                if (t < 32) {
                    float v[7];
                    float mx = NEG_INF;
                    #pragma unroll
                    for (int j = 0; j < 7; j++) {
                        int idx = j * 32 + lane;
                        v[j] = (idx < SS) ? cw[idx] : NEG_INF;
                        mx = fmaxf(mx, v[j]);
                    }
                    mx = warp_max(mx);
                    float sum = 0.f;
                    #pragma unroll
                    for (int j = 0; j < 7; j++) {
                        v[j] = (j * 32 + lane < SS) ? __expf(v[j] - mx) : 0.f;
                        sum += v[j];
                    }
                    sum = warp_sum(sum);
                    float inv = 1.f / sum;
                    #pragma unroll
                    for (int j = 0; j < 7; j++) {
                        int idx = j * 32 + lane;
                        if (idx < SS) swt[idx] = v[j] * inv * mskf[idx];
                    }
                }
                BARG();
            }

            // cap partials: 32 col-groups x 16 s-slices
            {
                int g = t & 31, sl = t >> 5;
                float4 acc = make_float4(0.f, 0.f, 0.f, 0.f);
                for (int s2 = sl; s2 < SS; s2 += 16) {
                    float sv = swt[s2];
                    float4 hv = hs4[s2 * 32 + g];
                    acc.x = fmaf(sv, hv.x, acc.x);
                    acc.y = fmaf(sv, hv.y, acc.y);
                    acc.z = fmaf(sv, hv.z, acc.z);
                    acc.w = fmaf(sv, hv.w, acc.w);
                }
                capp4[sl * 32 + g] = acc;
            }
            BARG();

            // last hat read for it2 done -> prefetch next item
            if (it == 2 && wn < NITEM && t == 0) {
                mbar_expect_tx(mbar, HATB);
                bulk_g2s(hsb, g_hat + (size_t)wn * SH, HATB, mbar);
            }

            // reduce + squash (warp 0 of group)
            if (t < 32) {
                float4 r = make_float4(0.f, 0.f, 0.f, 0.f);
                #pragma unroll
                for (int sl = 0; sl < 16; sl++) {
                    float4 tv = capp4[sl * 32 + t];
                    r.x += tv.x; r.y += tv.y; r.z += tv.z; r.w += tv.w;
                }
                float np = r.x * r.x + r.y * r.y + r.z * r.z + r.w * r.w;
                float nn = warp_sum(np);
                float f = nn / (1.f + nn) * rsqrtf(nn + 1e-9f);
                cap4[t] = make_float4(r.x * f, r.y * f, r.z * f, r.w * f);
            }
            BARG();

            // delta: per-thread dot, t-swizzled j (conflict-free)
            if (it < 2) {
                if (t < SS) {
                    const float4* hrow = hs4 + t * 32;
                    float a0 = 0.f, a1 = 0.f, a2 = 0.f, a3 = 0.f;
                    #pragma unroll 8
                    for (int j0 = 0; j0 < 32; j0++) {
                        int j = (j0 + t) & 31;
                        float4 hv = hrow[j];
                        float4 cv = cap4[j];
                        a0 = fmaf(hv.x, cv.x, a0);
                        a1 = fmaf(hv.y, cv.y, a1);
                        a2 = fmaf(hv.z, cv.z, a2);
                        a3 = fmaf(hv.w, cv.w, a3);
                    }
                    float d = (a0 + a1) + (a2 + a3);
                    cw[t] = (it == 0) ? d : cw[t] + d;
                }
                BARG();
            }
        }

        if (t < 128)
            out[(size_t)w * HH + t] = capf[t];
        BARG();
    }
    #undef BARG
}

// ---------------------------------------------------------------------------
extern "C" void kernel_launch(void* const* d_in, const int* in_sizes, int n_in,
                              void* d_out, int out_size)
{
    const float* item = (const float*)d_in[0];
    const int*   mask = (const int*)d_in[1];
    const float* w    = (const float*)d_in[2];
    float*       out  = (float*)d_out;

    cudaFuncSetAttribute(gemm_hat_mma,
                         cudaFuncAttributeMaxDynamicSharedMemorySize, SMEM_GEMM);
    cudaFuncSetAttribute(routing_kernel,
                         cudaFuncAttributeMaxDynamicSharedMemorySize, SMEM_ROUTE);

    dim3 ggrid(64, SS);
    gemm_hat_mma<<<ggrid, 256, SMEM_GEMM>>>(item, w);

    routing_kernel<<<NBLK, 1024, SMEM_ROUTE>>>(mask, out);
}

// round 17
// speedup vs baseline: 1.0998x; 1.0163x over previous
#include <cuda_runtime.h>
#include <cuda_bf16.h>
#include <math.h>
#include <stdint.h>

#define BB 1024
#define SS 200
#define II 4
#define HH 128
#define SH (SS*HH)          // 25600
#define WS (II*HH*HH)       // 65536
#define NITEM (BB*II)

__device__ float g_hat[(size_t)BB * II * SS * HH];   // [b][i][s][h], 419 MB

// ---------------------------------------------------------------------------
// helpers (plain sm_103-legal PTX only)
// ---------------------------------------------------------------------------
__device__ __forceinline__ uint32_t smem_u32(const void* p) {
    uint32_t a;
    asm("{ .reg .u64 t; cvta.to.shared.u64 t, %1; cvt.u32.u64 %0, t; }"
        : "=r"(a) : "l"(p));
    return a;
}
__device__ __forceinline__ void ldm4(uint32_t* r, uint32_t addr) {
    asm volatile("ldmatrix.sync.aligned.m8n8.x4.shared.b16 {%0,%1,%2,%3}, [%4];"
        : "=r"(r[0]), "=r"(r[1]), "=r"(r[2]), "=r"(r[3]) : "r"(addr));
}
__device__ __forceinline__ void mma16816(float* c, const uint32_t* a, const uint32_t* b) {
    asm volatile(
        "mma.sync.aligned.m16n8k16.row.col.f32.bf16.bf16.f32 "
        "{%0,%1,%2,%3}, {%4,%5,%6,%7}, {%8,%9}, {%0,%1,%2,%3};"
        : "+f"(c[0]), "+f"(c[1]), "+f"(c[2]), "+f"(c[3])
        : "r"(a[0]), "r"(a[1]), "r"(a[2]), "r"(a[3]), "r"(b[0]), "r"(b[1]));
}
__device__ __forceinline__ void mbar_init(uint32_t mbar, uint32_t cnt) {
    asm volatile("mbarrier.init.shared.b64 [%0], %1;" :: "r"(mbar), "r"(cnt) : "memory");
}
__device__ __forceinline__ void mbar_expect_tx(uint32_t mbar, uint32_t bytes) {
    asm volatile("mbarrier.arrive.expect_tx.shared.b64 _, [%0], %1;"
                 :: "r"(mbar), "r"(bytes) : "memory");
}
__device__ __forceinline__ void mbar_wait(uint32_t mbar, uint32_t parity) {
    asm volatile("{\n\t.reg .pred P;\n\t"
        "W_%=:\n\t"
        "mbarrier.try_wait.parity.acquire.cta.shared::cta.b64 P, [%0], %1, 0x989680;\n\t"
        "@P bra.uni D_%=;\n\t"
        "bra.uni W_%=;\n\t"
        "D_%=:\n\t}" :: "r"(mbar), "r"(parity) : "memory");
}
__device__ __forceinline__ void bulk_g2s(uint32_t dst, const void* src,
                                         uint32_t bytes, uint32_t mbar) {
    asm volatile(
        "cp.async.bulk.shared::cta.global.mbarrier::complete_tx::bytes [%0], [%1], %2, [%3];"
        :: "r"(dst), "l"(src), "r"(bytes), "r"(mbar) : "memory");
}
__device__ __forceinline__ float warp_sum(float v) {
    #pragma unroll
    for (int o = 16; o > 0; o >>= 1) v += __shfl_xor_sync(0xffffffffu, v, o);
    return v;
}
__device__ __forceinline__ float warp_max(float v) {
    #pragma unroll
    for (int o = 16; o > 0; o >>= 1) v = fmaxf(v, __shfl_xor_sync(0xffffffffu, v, o));
    return v;
}

// ---------------------------------------------------------------------------
// Phase 1: bf16-split HMMA GEMM (R16 verbatim — at mma.sync pipe floor).
// ---------------------------------------------------------------------------
#define PITCH 136
#define AT_B (128 * PITCH * 2)
#define BT_B (64  * PITCH * 2)
#define A_HI 0
#define A_LO (AT_B)
#define B_HI (2*AT_B)
#define B_LO (2*AT_B + BT_B)
#define SMEM_GEMM (2*AT_B + 2*BT_B)   // 104448

__device__ __forceinline__ uint32_t pack2(__nv_bfloat16 a, __nv_bfloat16 b) {
    __nv_bfloat162 t; t.x = a; t.y = b;
    return *(uint32_t*)&t;
}
__device__ __forceinline__ void split_store(char* hi, char* lo, int row, int k, float4 v) {
    __nv_bfloat16 h0 = __float2bfloat16(v.x), h1 = __float2bfloat16(v.y);
    __nv_bfloat16 h2 = __float2bfloat16(v.z), h3 = __float2bfloat16(v.w);
    __nv_bfloat16 l0 = __float2bfloat16(v.x - __bfloat162float(h0));
    __nv_bfloat16 l1 = __float2bfloat16(v.y - __bfloat162float(h1));
    __nv_bfloat16 l2 = __float2bfloat16(v.z - __bfloat162float(h2));
    __nv_bfloat16 l3 = __float2bfloat16(v.w - __bfloat162float(h3));
    uint32_t off = (uint32_t)row * (PITCH*2) + (uint32_t)k * 2;
    *(uint2*)(hi + off) = make_uint2(pack2(h0, h1), pack2(h2, h3));
    *(uint2*)(lo + off) = make_uint2(pack2(l0, l1), pack2(l2, l3));
}

__global__ __launch_bounds__(256, 2)
void gemm_hat_mma(const float* __restrict__ item, const float* __restrict__ w)
{
    extern __shared__ __align__(16) char smp[];
    const uint32_t sbase = smem_u32(smp);

    const int tid   = threadIdx.x;
    const int wid   = tid >> 5;
    const int lane  = tid & 31;
    const int btile = blockIdx.x >> 3;
    const int jt    = blockIdx.x & 7;
    const int s     = blockIdx.y;
    const int b0    = btile << 7;
    const int cap_i = jt >> 1;

    const float* ga = item + (size_t)b0 * SH + (size_t)s * HH;
    const float* gw = w + (size_t)s * WS + (size_t)jt * (64 * HH);
    #pragma unroll
    for (int q = 0; q < 8; q++) {
        int idx = q * 512 + tid;
        int row = idx >> 5;
        int k4  = (idx & 31) << 2;
        float4 av = *(const float4*)(ga + (size_t)row * SH + k4);
        split_store(smp + A_HI, smp + A_LO, row, k4, av);
        int idx2 = idx + 256;
        int row2 = idx2 >> 5;
        int k42  = (idx2 & 31) << 2;
        float4 av2 = *(const float4*)(ga + (size_t)row2 * SH + k42);
        split_store(smp + A_HI, smp + A_LO, row2, k42, av2);
    }
    #pragma unroll
    for (int q = 0; q < 8; q++) {
        int idx = q * 256 + tid;
        int row = idx >> 5;
        int k4  = (idx & 31) << 2;
        float4 wv = *(const float4*)(gw + row * HH + k4);
        split_store(smp + B_HI, smp + B_LO, row, k4, wv);
    }
    __syncthreads();

    const int mw = (wid & 3) * 32;
    const int nw = (wid >> 2) * 32;

    float acc[2][4][4];
    #pragma unroll
    for (int mt = 0; mt < 2; mt++)
        #pragma unroll
        for (int nt = 0; nt < 4; nt++)
            #pragma unroll
            for (int c = 0; c < 4; c++) acc[mt][nt][c] = 0.f;

    #pragma unroll
    for (int ks = 0; ks < 8; ks++) {
        const int k0 = ks * 16;
        uint32_t ah[2][4], al[2][4];
        {
            uint32_t aoff = (uint32_t)(mw + (lane & 15)) * (PITCH*2)
                          + (uint32_t)(k0 + ((lane >> 4) << 3)) * 2;
            ldm4(ah[0], sbase + A_HI + aoff);
            ldm4(ah[1], sbase + A_HI + aoff + 16 * (PITCH*2));
            ldm4(al[0], sbase + A_LO + aoff);
            ldm4(al[1], sbase + A_LO + aoff + 16 * (PITCH*2));
        }
        uint32_t bh[2][4], bl[2][4];
        {
            uint32_t boff = (uint32_t)(nw + ((lane >> 4) << 3) + (lane & 7)) * (PITCH*2)
                          + (uint32_t)(k0 + (((lane >> 3) & 1) << 3)) * 2;
            #pragma unroll
            for (int p = 0; p < 2; p++) {
                ldm4(bh[p], sbase + B_HI + boff + (uint32_t)p * 16 * (PITCH*2));
                ldm4(bl[p], sbase + B_LO + boff + (uint32_t)p * 16 * (PITCH*2));
            }
        }
        // product-major: consecutive mmas target 8 distinct accumulators;
        // per-accumulator order stays hh -> hl -> lh (bit-identical result)
        #pragma unroll
        for (int p = 0; p < 3; p++) {
            #pragma unroll
            for (int mt = 0; mt < 2; mt++)
                #pragma unroll
                for (int nt = 0; nt < 4; nt++) {
                    const uint32_t* ap = (p == 2) ? al[mt] : ah[mt];
                    const uint32_t* bp = (p == 1) ? &bl[nt >> 1][(nt & 1) * 2]
                                                  : &bh[nt >> 1][(nt & 1) * 2];
                    mma16816(acc[mt][nt], ap, bp);
                }
        }
    }

    const int g = lane >> 2, t = lane & 3;
    const int hbase = (jt & 1) * 64 + nw;
    #pragma unroll
    for (int mt = 0; mt < 2; mt++) {
        int rowm = mw + mt * 16 + g;
        size_t p0 = ((size_t)(b0 + rowm) * II + cap_i) * SH + (size_t)s * HH + hbase;
        size_t p1 = p0 + (size_t)8 * II * SH;
        #pragma unroll
        for (int nt = 0; nt < 4; nt++) {
            *(float2*)(g_hat + p0 + nt * 8 + 2 * t) =
                make_float2(acc[mt][nt][0], acc[mt][nt][1]);
            *(float2*)(g_hat + p1 + nt * 8 + 2 * t) =
                make_float2(acc[mt][nt][2], acc[mt][nt][3]);
        }
    }
}

// ---------------------------------------------------------------------------
// Phase 2: routing — R11 chain, but 296 CTAs x 512 threads (1 chain/CTA,
// plain __syncthreads instead of named barriers) + trailing barrier removed.
// ---------------------------------------------------------------------------
#define NBLK2 296
#define HATB (SS*HH*4)
#define G_HAT  0
#define G_CAPP (SS*HH)                 // [16][128]
#define G_CW   (G_CAPP + 2048)
#define G_SWT  (G_CW + SS)
#define G_MSK  (G_SWT + SS)
#define G_CAP  (G_MSK + SS)            // float idx 28248 -> byte 112992, 16B-aligned
#define GSZ    (G_CAP + 128)           // 28376 floats = 113504 B
#define R_MB   (GSZ * 4)
#define SMEM_ROUTE (R_MB + 16)         // 113520 B -> 2 CTA/SM

__global__ __launch_bounds__(512, 2)
void routing_kernel(const int* __restrict__ mask, float* __restrict__ out)
{
    extern __shared__ __align__(16) float sm[];
    const uint32_t sb = smem_u32(sm);

    const int t    = threadIdx.x;
    const int lane = t & 31;

    float4* hs4   = (float4*)(sm + G_HAT);
    float4* capp4 = (float4*)(sm + G_CAPP);
    float*  cw    = sm + G_CW;
    float*  swt   = sm + G_SWT;
    float*  mskf  = sm + G_MSK;
    float4* cap4  = (float4*)(sm + G_CAP);
    float*  capf  = sm + G_CAP;
    const uint32_t mbar = sb + R_MB;

    if (t == 0) {
        mbar_init(mbar, 1);
        asm volatile("fence.proxy.async.shared::cta;" ::: "memory");
    }
    __syncthreads();

    const float NEG_INF = __int_as_float(0xff800000);
    uint32_t phase = 0;
    const int worker = blockIdx.x;

    if (t == 0) {
        mbar_expect_tx(mbar, HATB);
        bulk_g2s(sb + G_HAT * 4, g_hat + (size_t)worker * SH, HATB, mbar);
    }

    for (int w = worker; w < NITEM; w += NBLK2) {
        const int my_mask = (t < SS) ? mask[(w >> 2) * SS + t] : 0;
        if (t < SS) mskf[t] = my_mask ? 1.f : 0.f;   // ordered by it0's sync
        const int wn = w + NBLK2;

        mbar_wait(mbar, phase);
        phase ^= 1;

        for (int it = 0; it < 3; it++) {
            if (it == 0) {
                // cw == 0 -> uniform softmax, then masked
                if (t < SS) swt[t] = my_mask ? (1.f / SS) : 0.f;
                __syncthreads();
            } else {
                // single-warp softmax: warp 0 holds all 200 cw in registers
                if (t < 32) {
                    float v[7];
                    float mx = NEG_INF;
                    #pragma unroll
                    for (int j = 0; j < 7; j++) {
                        int idx = j * 32 + lane;
                        v[j] = (idx < SS) ? cw[idx] : NEG_INF;
                        mx = fmaxf(mx, v[j]);
                    }
                    mx = warp_max(mx);
                    float sum = 0.f;
                    #pragma unroll
                    for (int j = 0; j < 7; j++) {
                        v[j] = (j * 32 + lane < SS) ? __expf(v[j] - mx) : 0.f;
                        sum += v[j];
                    }
                    sum = warp_sum(sum);
                    float inv = 1.f / sum;
                    #pragma unroll
                    for (int j = 0; j < 7; j++) {
                        int idx = j * 32 + lane;
                        if (idx < SS) swt[idx] = v[j] * inv * mskf[idx];
                    }
                }
                __syncthreads();
            }

            // cap partials: 32 col-groups x 16 s-slices
            {
                int g = t & 31, sl = t >> 5;
                float4 acc = make_float4(0.f, 0.f, 0.f, 0.f);
                for (int s2 = sl; s2 < SS; s2 += 16) {
                    float sv = swt[s2];
                    float4 hv = hs4[s2 * 32 + g];
                    acc.x = fmaf(sv, hv.x, acc.x);
                    acc.y = fmaf(sv, hv.y, acc.y);
                    acc.z = fmaf(sv, hv.z, acc.z);
                    acc.w = fmaf(sv, hv.w, acc.w);
                }
                capp4[sl * 32 + g] = acc;
            }
            __syncthreads();

            // last hat read for it2 done -> prefetch next item
            if (it == 2 && wn < NITEM && t == 0) {
                mbar_expect_tx(mbar, HATB);
                bulk_g2s(sb + G_HAT * 4, g_hat + (size_t)wn * SH, HATB, mbar);
            }

            // reduce + squash (warp 0)
            if (t < 32) {
                float4 r = make_float4(0.f, 0.f, 0.f, 0.f);
                #pragma unroll
                for (int sl = 0; sl < 16; sl++) {
                    float4 tv = capp4[sl * 32 + t];
                    r.x += tv.x; r.y += tv.y; r.z += tv.z; r.w += tv.w;
                }
                float np = r.x * r.x + r.y * r.y + r.z * r.z + r.w * r.w;
                float nn = warp_sum(np);
                float f = nn / (1.f + nn) * rsqrtf(nn + 1e-9f);
                cap4[t] = make_float4(r.x * f, r.y * f, r.z * f, r.w * f);
            }
            __syncthreads();

            // delta: per-thread dot, t-swizzled j (conflict-free)
            if (it < 2) {
                if (t < SS) {
                    const float4* hrow = hs4 + t * 32;
                    float a0 = 0.f, a1 = 0.f, a2 = 0.f, a3 = 0.f;
                    #pragma unroll 8
                    for (int j0 = 0; j0 < 32; j0++) {
                        int j = (j0 + t) & 31;
                        float4 hv = hrow[j];
                        float4 cv = cap4[j];
                        a0 = fmaf(hv.x, cv.x, a0);
                        a1 = fmaf(hv.y, cv.y, a1);
                        a2 = fmaf(hv.z, cv.z, a2);
                        a3 = fmaf(hv.w, cv.w, a3);
                    }
                    float d = (a0 + a1) + (a2 + a3);
                    cw[t] = (it == 0) ? d : cw[t] + d;
                }
                __syncthreads();
            }
        }

        if (t < 128)
            out[(size_t)w * HH + t] = capf[t];
        // no trailing barrier: capf/capp4/swt/mskf are each >=2 syncs away
        // from their next writer; hat-buffer reuse is gated by mbar_wait.
    }
}

// ---------------------------------------------------------------------------
extern "C" void kernel_launch(void* const* d_in, const int* in_sizes, int n_in,
                              void* d_out, int out_size)
{
    const float* item = (const float*)d_in[0];
    const int*   mask = (const int*)d_in[1];
    const float* w    = (const float*)d_in[2];
    float*       out  = (float*)d_out;

    cudaFuncSetAttribute(gemm_hat_mma,
                         cudaFuncAttributeMaxDynamicSharedMemorySize, SMEM_GEMM);
    cudaFuncSetAttribute(routing_kernel,
                         cudaFuncAttributeMaxDynamicSharedMemorySize, SMEM_ROUTE);

    dim3 ggrid(64, SS);
    gemm_hat_mma<<<ggrid, 256, SMEM_GEMM>>>(item, w);

    routing_kernel<<<NBLK2, 512, SMEM_ROUTE>>>(mask, out);
}